// round 1
// baseline (speedup 1.0000x reference)
#include <cuda_runtime.h>
#include <cuda_bf16.h>
#include <math.h>

#define B_  32
#define T_  256
#define D_  1024
#define D3_ 3072
#define TB_ 8192
#define L_  2

// ---------------- device scratch (globals: allocation-free) ----------------
__device__ __nv_bfloat16 g_Wih_bf[2*L_*D3_*D_];   // [dir][layer][3072][1024]
__device__ __nv_bfloat16 g_Whh_bf[2*L_*D3_*D_];
__device__ __nv_bfloat16 g_x_bf [TB_*D_];         // layer-0 input  [T*B][D]
__device__ __nv_bfloat16 g_yf_bf[TB_*D_];         // fwd stack layer output
__device__ __nv_bfloat16 g_yb_bf[TB_*D_];         // bwd stack layer output
__device__ float         g_xg[2][TB_*D3_];        // per-dir input gates
__device__ float         g_h  [2*B_*D_];          // fp32 hidden state [stack][B][D]
__device__ __nv_bfloat16 g_hbf[2][2*B_*D_];       // bf16 h, ping-pong by phase
__device__ float         g_outvals[TB_];

// mma.sync m16n8k16 row.col f32.bf16.bf16.f32
#define MMA_BF16(d, a0,a1,a2,a3, b0,b1) \
  asm volatile("mma.sync.aligned.m16n8k16.row.col.f32.bf16.bf16.f32 " \
    "{%0,%1,%2,%3},{%4,%5,%6,%7},{%8,%9},{%0,%1,%2,%3};\n" \
    : "+f"(d[0]), "+f"(d[1]), "+f"(d[2]), "+f"(d[3]) \
    : "r"(a0), "r"(a1), "r"(a2), "r"(a3), "r"(b0), "r"(b1))

// ---------------- weight conversion fp32 -> bf16 ----------------
__global__ void k_convw(const float* __restrict__ Wih_f, const float* __restrict__ Whh_f,
                        const float* __restrict__ Wih_b, const float* __restrict__ Whh_b) {
  const int N = L_*D3_*D_;
  for (int i = blockIdx.x*blockDim.x + threadIdx.x; i < N; i += gridDim.x*blockDim.x) {
    g_Wih_bf[i]     = __float2bfloat16(Wih_f[i]);
    g_Wih_bf[N + i] = __float2bfloat16(Wih_b[i]);
    g_Whh_bf[i]     = __float2bfloat16(Whh_f[i]);
    g_Whh_bf[N + i] = __float2bfloat16(Whh_b[i]);
  }
}

// ---------------- input projections + concat -> x[T*B][D] bf16 ----------------
__global__ __launch_bounds__(256) void k_proj(const float* __restrict__ input, const float* __restrict__ cond,
    const float* __restrict__ Wc, const float* __restrict__ bc,
    const float* __restrict__ Wi, const float* __restrict__ bi) {
  int t = blockIdx.x;          // one timestep per block; 32 batches
  int tid = threadIdx.x;
  __shared__ float cond_s[B_][80];
  __shared__ float in_s[B_][72];
  __shared__ float wbuf[64][80];
  __shared__ float bias_s[64];
  for (int i = tid; i < B_*80; i += 256) {
    int b = i / 80, j = i % 80;
    cond_s[b][j] = cond[((size_t)b*T_ + t)*80 + j];
  }
  for (int i = tid; i < B_*72; i += 256) {
    int b = i / 72, j = i % 72;
    in_s[b][j] = input[((size_t)b*T_ + t)*72 + j];
  }
  __syncthreads();
  for (int chunk = 0; chunk < 16; chunk++) {
    int dbase = chunk*64;
    int width = (dbase < 512) ? 80 : 72;
    const float* Wsrc = (dbase < 512) ? (Wc + (size_t)dbase*80) : (Wi + (size_t)(dbase-512)*72);
    for (int i = tid; i < 64*width; i += 256) wbuf[i/width][i%width] = Wsrc[i];
    if (tid < 64) bias_s[tid] = (dbase < 512) ? bc[dbase+tid] : bi[dbase-512+tid];
    __syncthreads();
    for (int i = tid; i < B_*64; i += 256) {
      int b = i & 31, dd = i >> 5;
      const float* act = (dbase < 512) ? &cond_s[b][0] : &in_s[b][0];
      float a = bias_s[dd];
      const float* w = &wbuf[dd][0];
      #pragma unroll 8
      for (int j = 0; j < width; j++) a += w[j]*act[j];
      a = fmaxf(a, 0.f);
      g_x_bf[((size_t)t*B_ + b)*D_ + dbase + dd] = __float2bfloat16(a);
    }
    __syncthreads();
  }
}

// ---------------- xg = A @ Wih^T + bih   (M=8192, N=3072, K=1024, bf16 mma) ----------------
__global__ __launch_bounds__(256) void k_gemm(int layer,
    const float* __restrict__ bih_f, const float* __restrict__ bih_b) {
  int dir = blockIdx.z;
  const __nv_bfloat16* A = (layer == 0) ? g_x_bf : (dir ? g_yb_bf : g_yf_bf);
  const __nv_bfloat16* W = g_Wih_bf + (size_t)(dir*L_ + layer)*D3_*D_;
  const float* bias = (dir ? bih_b : bih_f) + (size_t)layer*D3_;
  float* C = g_xg[dir];
  int m0 = blockIdx.y*128, n0 = blockIdx.x*64;

  __shared__ alignas(16) __nv_bfloat16 As[2][128][40];
  __shared__ alignas(16) __nv_bfloat16 Bs[2][64][40];

  int tid = threadIdx.x, lane = tid&31, warp = tid>>5;
  int wm = warp>>1, wn = warp&1, tg = lane>>2, tc = lane&3;
  int lr = tid>>2, lc = (tid&3)*8;

  float acc[2][4][4];
  #pragma unroll
  for (int i=0;i<2;i++)
    #pragma unroll
    for(int j=0;j<4;j++)
      #pragma unroll
      for(int k=0;k<4;k++) acc[i][j][k]=0.f;

  uint4 va0, va1, vb0;
  // prologue: chunk 0
  va0 = *(const uint4*)&A[(size_t)(m0+lr)*D_ + lc];
  va1 = *(const uint4*)&A[(size_t)(m0+lr+64)*D_ + lc];
  vb0 = *(const uint4*)&W[(size_t)(n0+lr)*D_ + lc];
  *(uint4*)&As[0][lr][lc]    = va0;
  *(uint4*)&As[0][lr+64][lc] = va1;
  *(uint4*)&Bs[0][lr][lc]    = vb0;
  __syncthreads();

  int cur = 0;
  for (int it = 0; it < 32; it++) {
    if (it < 31) {
      int kc = (it+1)*32;
      va0 = *(const uint4*)&A[(size_t)(m0+lr)*D_ + kc + lc];
      va1 = *(const uint4*)&A[(size_t)(m0+lr+64)*D_ + kc + lc];
      vb0 = *(const uint4*)&W[(size_t)(n0+lr)*D_ + kc + lc];
    }
    #pragma unroll
    for (int s = 0; s < 32; s += 16) {
      unsigned a[2][4];
      #pragma unroll
      for (int mt = 0; mt < 2; mt++) {
        int r = wm*32 + mt*16 + tg;
        a[mt][0] = *(const unsigned*)&As[cur][r  ][s + 2*tc];
        a[mt][1] = *(const unsigned*)&As[cur][r+8][s + 2*tc];
        a[mt][2] = *(const unsigned*)&As[cur][r  ][s + 2*tc + 8];
        a[mt][3] = *(const unsigned*)&As[cur][r+8][s + 2*tc + 8];
      }
      #pragma unroll
      for (int nt = 0; nt < 4; nt++) {
        int nr = wn*32 + nt*8 + tg;
        unsigned b0 = *(const unsigned*)&Bs[cur][nr][s + 2*tc];
        unsigned b1 = *(const unsigned*)&Bs[cur][nr][s + 2*tc + 8];
        MMA_BF16(acc[0][nt], a[0][0],a[0][1],a[0][2],a[0][3], b0, b1);
        MMA_BF16(acc[1][nt], a[1][0],a[1][1],a[1][2],a[1][3], b0, b1);
      }
    }
    if (it < 31) {
      int nxt = cur^1;
      *(uint4*)&As[nxt][lr][lc]    = va0;
      *(uint4*)&As[nxt][lr+64][lc] = va1;
      *(uint4*)&Bs[nxt][lr][lc]    = vb0;
    }
    __syncthreads();
    cur ^= 1;
  }

  #pragma unroll
  for (int mt=0; mt<2; mt++) {
    #pragma unroll
    for (int nt=0; nt<4; nt++) {
      int gr = m0 + wm*32 + mt*16 + tg;
      int gc = n0 + wn*32 + nt*8 + 2*tc;
      C[(size_t)gr*D3_ + gc]       = acc[mt][nt][0] + bias[gc];
      C[(size_t)gr*D3_ + gc + 1]   = acc[mt][nt][1] + bias[gc+1];
      C[(size_t)(gr+8)*D3_ + gc]   = acc[mt][nt][2] + bias[gc];
      C[(size_t)(gr+8)*D3_ + gc+1] = acc[mt][nt][3] + bias[gc+1];
    }
  }
}

// ---------------- zero hidden state ----------------
__global__ void k_hinit() {
  int i = blockIdx.x*blockDim.x + threadIdx.x;
  if (i < 2*B_*D_) {
    g_h[i] = 0.f;
    g_hbf[0][i] = __float2bfloat16(0.f);
    g_hbf[1][i] = __float2bfloat16(0.f);
  }
}

// ---------------- one GRU timestep, both stacks ----------------
// grid 128: stack = bid>>6, col-block of 16 h-columns = bid&63. block 128 threads.
__global__ __launch_bounds__(128) void k_step(int t, int layer, int phase,
    const float* __restrict__ bhh_f, const float* __restrict__ bhh_b) {
  int stack = blockIdx.x >> 6;
  int blk   = blockIdx.x & 63;
  int cgb   = blk * 16;
  const __nv_bfloat16* Whh = g_Whh_bf + (size_t)(stack*L_ + layer)*D3_*D_;
  const float* xg = g_xg[stack];
  const float* bhh = (stack ? bhh_b : bhh_f) + (size_t)layer*D3_;
  __nv_bfloat16* ys = stack ? g_yb_bf : g_yf_bf;
  float* h = g_h + (size_t)stack*B_*D_;
  const __nv_bfloat16* hin = g_hbf[phase]     + (size_t)stack*B_*D_;
  __nv_bfloat16*       hout= g_hbf[phase ^ 1] + (size_t)stack*B_*D_;

  __shared__ alignas(16) __nv_bfloat16 hs[2][32][72];
  __shared__ alignas(16) __nv_bfloat16 Ws[2][48][72];
  __shared__ float hg_s[32][52];

  int tid = threadIdx.x, lane = tid&31, warp = tid>>5;
  int wm = warp & 1, wn = warp >> 1, tg = lane>>2, tc = lane&3;
  int hr0 = tid>>3, hseg = (tid&7)*8;   // hr0 in 0..15

  float acc[3][4];
  #pragma unroll
  for (int i=0;i<3;i++)
    #pragma unroll
    for (int j=0;j<4;j++) acc[i][j]=0.f;

  uint4 vh0, vh1, vw0, vw1, vw2;
  // prologue chunk 0 (K chunk = 64)
  vh0 = *(const uint4*)&hin[(size_t)hr0*D_ + hseg];
  vh1 = *(const uint4*)&hin[(size_t)(hr0+16)*D_ + hseg];
  vw0 = *(const uint4*)&Whh[(size_t)(        cgb + hr0)*D_ + hseg];
  vw1 = *(const uint4*)&Whh[(size_t)(D_   + cgb + hr0)*D_ + hseg];
  vw2 = *(const uint4*)&Whh[(size_t)(2*D_ + cgb + hr0)*D_ + hseg];
  *(uint4*)&hs[0][hr0][hseg]     = vh0;
  *(uint4*)&hs[0][hr0+16][hseg]  = vh1;
  *(uint4*)&Ws[0][hr0][hseg]     = vw0;
  *(uint4*)&Ws[0][hr0+16][hseg]  = vw1;
  *(uint4*)&Ws[0][hr0+32][hseg]  = vw2;
  __syncthreads();

  int cur = 0;
  for (int it = 0; it < 16; it++) {
    if (it < 15) {
      int kc = (it+1)*64;
      vh0 = *(const uint4*)&hin[(size_t)hr0*D_ + kc + hseg];
      vh1 = *(const uint4*)&hin[(size_t)(hr0+16)*D_ + kc + hseg];
      vw0 = *(const uint4*)&Whh[(size_t)(        cgb + hr0)*D_ + kc + hseg];
      vw1 = *(const uint4*)&Whh[(size_t)(D_   + cgb + hr0)*D_ + kc + hseg];
      vw2 = *(const uint4*)&Whh[(size_t)(2*D_ + cgb + hr0)*D_ + kc + hseg];
    }
    #pragma unroll
    for (int s = 0; s < 64; s += 16) {
      unsigned a0 = *(const unsigned*)&hs[cur][wm*16+tg  ][s + 2*tc];
      unsigned a1 = *(const unsigned*)&hs[cur][wm*16+tg+8][s + 2*tc];
      unsigned a2 = *(const unsigned*)&hs[cur][wm*16+tg  ][s + 2*tc + 8];
      unsigned a3 = *(const unsigned*)&hs[cur][wm*16+tg+8][s + 2*tc + 8];
      #pragma unroll
      for (int nt = 0; nt < 3; nt++) {
        int nr = wn*24 + nt*8 + tg;
        unsigned b0 = *(const unsigned*)&Ws[cur][nr][s + 2*tc];
        unsigned b1 = *(const unsigned*)&Ws[cur][nr][s + 2*tc + 8];
        MMA_BF16(acc[nt], a0,a1,a2,a3, b0,b1);
      }
    }
    if (it < 15) {
      int nxt = cur ^ 1;
      *(uint4*)&hs[nxt][hr0][hseg]     = vh0;
      *(uint4*)&hs[nxt][hr0+16][hseg]  = vh1;
      *(uint4*)&Ws[nxt][hr0][hseg]     = vw0;
      *(uint4*)&Ws[nxt][hr0+16][hseg]  = vw1;
      *(uint4*)&Ws[nxt][hr0+32][hseg]  = vw2;
    }
    __syncthreads();
    cur ^= 1;
  }

  // stage hg to SMEM for gate fusion
  #pragma unroll
  for (int nt = 0; nt < 3; nt++) {
    int col = wn*24 + nt*8 + 2*tc;
    int r0 = wm*16 + tg;
    hg_s[r0][col]     = acc[nt][0];
    hg_s[r0][col+1]   = acc[nt][1];
    hg_s[r0+8][col]   = acc[nt][2];
    hg_s[r0+8][col+1] = acc[nt][3];
  }
  __syncthreads();

  // gates: 32 batches x 16 columns
  for (int i = tid; i < 512; i += 128) {
    int b = i & 31, j = i >> 5;
    int cg = cgb + j;
    size_t row = (size_t)t*B_ + b;
    float xr = xg[row*D3_ + cg];
    float xz = xg[row*D3_ + D_ + cg];
    float xn = xg[row*D3_ + 2*D_ + cg];
    float hr = hg_s[b][j]    + bhh[cg];
    float hz = hg_s[b][16+j] + bhh[D_+cg];
    float hn = hg_s[b][32+j] + bhh[2*D_+cg];
    float r  = 1.f/(1.f + __expf(-(xr+hr)));
    float z  = 1.f/(1.f + __expf(-(xz+hz)));
    float nn = tanhf(xn + r*hn);
    float hp = h[(size_t)b*D_ + cg];
    float hnew = (1.f - z)*nn + z*hp;
    h[(size_t)b*D_ + cg] = hnew;
    __nv_bfloat16 hb = __float2bfloat16(hnew);
    hout[(size_t)b*D_ + cg] = hb;
    ys[row*D_ + cg] = hb;
  }
}

// ---------------- output head ----------------
__global__ __launch_bounds__(128) void k_out1(const float* __restrict__ Wo, const float* __restrict__ bo) {
  int row = blockIdx.x;
  int tid = threadIdx.x;
  float acc = 0.f;
  for (int d = tid; d < D_; d += 128)
    acc += (__bfloat162float(g_yf_bf[(size_t)row*D_+d]) +
            __bfloat162float(g_yb_bf[(size_t)row*D_+d])) * Wo[d];
  #pragma unroll
  for (int o = 16; o; o >>= 1) acc += __shfl_xor_sync(0xffffffffu, acc, o);
  __shared__ float ws[4];
  if ((tid & 31) == 0) ws[tid>>5] = acc;
  __syncthreads();
  if (tid == 0) {
    float s = ws[0]+ws[1]+ws[2]+ws[3] + bo[0];
    g_outvals[row] = 1.f/(1.f + expf(-s));
  }
}

__global__ void k_out2(float* out) {
  __shared__ float sm[256];
  int tid = threadIdx.x;
  float s = 0.f;
  for (int i = tid; i < TB_; i += 256) s += g_outvals[i];
  sm[tid] = s;
  __syncthreads();
  for (int o = 128; o; o >>= 1) { if (tid < o) sm[tid] += sm[tid+o]; __syncthreads(); }
  if (tid == 0) out[0] = sm[0] / (float)TB_;
}

// ---------------- launch ----------------
extern "C" void kernel_launch(void* const* d_in, const int* in_sizes, int n_in,
                              void* d_out, int out_size) {
  (void)in_sizes; (void)n_in; (void)out_size;
  const float* input = (const float*)d_in[0];
  const float* cond  = (const float*)d_in[1];
  const float* Wc    = (const float*)d_in[2];
  const float* bc    = (const float*)d_in[3];
  const float* Wi    = (const float*)d_in[4];
  const float* bi    = (const float*)d_in[5];
  const float* Wih_f = (const float*)d_in[6];
  const float* Whh_f = (const float*)d_in[7];
  const float* bih_f = (const float*)d_in[8];
  const float* bhh_f = (const float*)d_in[9];
  const float* Wih_b = (const float*)d_in[10];
  const float* Whh_b = (const float*)d_in[11];
  const float* bih_b = (const float*)d_in[12];
  const float* bhh_b = (const float*)d_in[13];
  const float* Wo    = (const float*)d_in[14];
  const float* bo    = (const float*)d_in[15];
  float* out = (float*)d_out;

  k_convw<<<4096, 256>>>(Wih_f, Whh_f, Wih_b, Whh_b);
  k_proj<<<256, 256>>>(input, cond, Wc, bc, Wi, bi);
  for (int l = 0; l < L_; l++) {
    k_gemm<<<dim3(48, 64, 2), 256>>>(l, bih_f, bih_b);
    k_hinit<<<(2*B_*D_ + 255)/256, 256>>>();
    for (int t = 0; t < T_; t++)
      k_step<<<128, 128>>>(t, l, t & 1, bhh_f, bhh_b);
  }
  k_out1<<<TB_, 128>>>(Wo, bo);
  k_out2<<<1, 256>>>(out);
}